// round 5
// baseline (speedup 1.0000x reference)
#include <cuda_runtime.h>
#include <cuda_bf16.h>

#define THICKNESS 0.00047f
#define MAX_V 1000000

// padded vertex scratch: posw[i] = (x, y, z, _), one 32B-sector gather each
__device__ float4 g_posw[MAX_V];

// 4 vertices per thread: 3 aligned float4 reads, 4 float4 writes
__global__ void pad_pos4_kernel(const float* __restrict__ pos, int V4, int V) {
    int j = blockIdx.x * blockDim.x + threadIdx.x;
    if (j < V4) {
        const float4* p = (const float4*)(pos + 12ll * j);
        float4 a = __ldcs(p);
        float4 b = __ldcs(p + 1);
        float4 c = __ldcs(p + 2);
        int v = 4 * j;
        g_posw[v + 0] = make_float4(a.x, a.y, a.z, 0.0f);
        g_posw[v + 1] = make_float4(a.w, b.x, b.y, 0.0f);
        g_posw[v + 2] = make_float4(b.z, b.w, c.x, 0.0f);
        g_posw[v + 3] = make_float4(c.y, c.z, c.w, 0.0f);
    } else {
        int v = 4 * V4 + (j - V4);
        if (v < V) {
            const float* b = pos + 3ll * v;
            g_posw[v] = make_float4(b[0], b[1], b[2], 0.0f);
        }
    }
}

__device__ __forceinline__ float face_energy(
    float4 p0, float4 p1, float4 p2, float4 dm, float ar, float mu, float lam)
{
    float d1x = p0.x - p2.x, d1y = p0.y - p2.y, d1z = p0.z - p2.z;
    float d2x = p1.x - p2.x, d2y = p1.y - p2.y, d2z = p1.z - p2.z;
    float a = dm.x, b = dm.y, c = dm.z, d = dm.w;
    float F0x = d1x * a + d2x * c;
    float F0y = d1y * a + d2y * c;
    float F0z = d1z * a + d2z * c;
    float F1x = d1x * b + d2x * d;
    float F1y = d1y * b + d2y * d;
    float F1z = d1z * b + d2z * d;
    float g00 = 0.5f * (F0x * F0x + F0y * F0y + F0z * F0z - 1.0f);
    float g01 = 0.5f * (F0x * F1x + F0y * F1y + F0z * F1z);
    float g11 = 0.5f * (F1x * F1x + F1y * F1y + F1z * F1z - 1.0f);
    float tr = g00 + g11;
    float s00 = mu * g00 + 0.5f * lam * tr;
    float s01 = mu * g01;
    float s11 = mu * g11 + 0.5f * lam * tr;
    float ed = s00 * g00 + 2.0f * s01 * g01 + s11 * g11;
    return ar * THICKNESS * ed;
}

__global__ void stvk_face4_kernel(
    const int* __restrict__ faces,        // [F,3] int32
    const float* __restrict__ dminv,      // [F,2,2]
    const float* __restrict__ area,       // [F,1]
    const float* __restrict__ mu_p,
    const float* __restrict__ lam_p,
    float* __restrict__ per_vert,         // [V]
    float* __restrict__ loss,
    int F4, int F)
{
    int t = blockIdx.x * blockDim.x + threadIdx.x;
    float esum = 0.0f;
    float mu = __ldg(mu_p);
    float lam = __ldg(lam_p);

    if (t < F4) {
        // 48B of indices for 4 faces: 3 aligned int4 streaming loads
        const int4* fp = (const int4*)(faces + 12ll * t);
        int4 A = __ldcs(fp);
        int4 B = __ldcs(fp + 1);
        int4 C = __ldcs(fp + 2);
        int idx[12] = {A.x, A.y, A.z, A.w, B.x, B.y, B.z, B.w, C.x, C.y, C.z, C.w};

        // 12 independent gathers in flight (MLP=12)
        float4 P[12];
        #pragma unroll
        for (int k = 0; k < 12; k++) P[k] = __ldg(&g_posw[idx[k]]);

        int f0 = 4 * t;
        float4 dm[4];
        #pragma unroll
        for (int k = 0; k < 4; k++) dm[k] = __ldcs((const float4*)dminv + f0 + k);
        float4 ar = __ldcs((const float4*)(area + f0));
        float arv[4] = {ar.x, ar.y, ar.z, ar.w};

        #pragma unroll
        for (int k = 0; k < 4; k++) {
            float e = face_energy(P[3 * k], P[3 * k + 1], P[3 * k + 2], dm[k], arv[k], mu, lam);
            esum += e;
            float e3 = e * (1.0f / 3.0f);
            atomicAdd(&per_vert[idx[3 * k + 0]], e3);
            atomicAdd(&per_vert[idx[3 * k + 1]], e3);
            atomicAdd(&per_vert[idx[3 * k + 2]], e3);
        }
    } else {
        // tail faces, scalar path
        int f = 4 * F4 + (t - F4);
        if (f < F) {
            const int* fr = faces + 3ll * f;
            int i0 = fr[0], i1 = fr[1], i2 = fr[2];
            float4 dmv = __ldg((const float4*)dminv + f);
            float e = face_energy(__ldg(&g_posw[i0]), __ldg(&g_posw[i1]), __ldg(&g_posw[i2]),
                                  dmv, __ldg(&area[f]), mu, lam);
            esum += e;
            float e3 = e * (1.0f / 3.0f);
            atomicAdd(&per_vert[i0], e3);
            atomicAdd(&per_vert[i1], e3);
            atomicAdd(&per_vert[i2], e3);
        }
    }

    // block-reduce esum -> one loss atomic per block
    float v = esum;
    #pragma unroll
    for (int off = 16; off > 0; off >>= 1)
        v += __shfl_down_sync(0xFFFFFFFFu, v, off);

    __shared__ float smem[8];
    int lane = threadIdx.x & 31;
    int wid = threadIdx.x >> 5;
    if (lane == 0) smem[wid] = v;
    __syncthreads();
    if (wid == 0) {
        float w = (lane < (blockDim.x >> 5)) ? smem[lane] : 0.0f;
        #pragma unroll
        for (int off = 4; off > 0; off >>= 1)
            w += __shfl_down_sync(0xFFFFFFFFu, w, off);
        if (lane == 0 && loss != nullptr)
            atomicAdd(loss, w);
    }
}

extern "C" void kernel_launch(void* const* d_in, const int* in_sizes, int n_in,
                              void* d_out, int out_size) {
    const float* pos = (const float*)d_in[0];
    const int* faces = (const int*)d_in[1];
    const float* dminv = (const float*)d_in[2];
    const float* area = (const float*)d_in[3];
    const float* mu_p = (const float*)d_in[4];
    const float* lam_p = (const float*)d_in[5];

    int V = in_sizes[0] / 3;
    int F = in_sizes[1] / 3;

    float* out = (float*)d_out;
    float* per_vert = out + (out_size - V);
    float* loss = (out_size > V) ? out : nullptr;

    cudaMemsetAsync(d_out, 0, (size_t)out_size * sizeof(float));

    int threads = 256;
    int V4 = V >> 2;
    int vrem = V & 3;
    int vT = V4 + vrem;
    pad_pos4_kernel<<<(vT + threads - 1) / threads, threads>>>(pos, V4, V);

    int F4 = F >> 2;
    int frem = F & 3;
    int fT = F4 + frem;
    stvk_face4_kernel<<<(fT + threads - 1) / threads, threads>>>(
        faces, dminv, area, mu_p, lam_p, per_vert, loss, F4, F);
}